// round 12
// baseline (speedup 1.0000x reference)
#include <cuda_runtime.h>
#include <cuda_fp16.h>
#include <cstdint>

typedef unsigned long long ull;
typedef unsigned int uint;

// Problem constants
#define BB   4
#define CC   128
#define HH   96
#define WW   96
#define OC   18          // G*K*K*2
#define HWP  (HH*WW)     // 9216
#define NPIX (BB*HWP)    // 36864
#define KCH  8           // split-K chunks for conv (16 channels each)
#define HP   98          // padded H (halo)
#define WP   98          // padded W (halo)

// ---------------- scratch (static device arrays; no allocation) ----------------
__device__ float  g_rotp[KCH * BB * OC * HWP];            // conv partial coord sums
__device__ float2 g_xt[(size_t)BB * HP * WP * 64];        // padded NHWC ch-paired

// ---------------- helpers ----------------
__device__ __forceinline__ void unpackf2(ull v, float& a, float& b) {
    asm("mov.b64 {%0, %1}, %2;" : "=f"(a), "=f"(b) : "l"(v));
}
__device__ __forceinline__ void fma2(ull& d, ull a, ull b) {
    asm("fma.rn.f32x2 %0, %1, %2, %0;" : "+l"(d) : "l"(a), "l"(b));
}
__device__ __forceinline__ ull mul2(ull a, ull b) {
    ull r; asm("mul.rn.f32x2 %0, %1, %2;" : "=l"(r) : "l"(a), "l"(b)); return r;
}
__device__ __forceinline__ ull add2(ull a, ull b) {
    ull r; asm("add.rn.f32x2 %0, %1, %2;" : "=l"(r) : "l"(a), "l"(b)); return r;
}
// fp16-pair -> packed f32x2 (storage-only quantization; math stays fp32)
__device__ __forceinline__ ull h2tof2(uint raw) {
    float2 f = __half22float2(*(const __half2*)&raw);
    return *(const ull*)&f;
}
__device__ __forceinline__ uint packh2(float a, float b) {
    __half2 hv = __floats2half2_rn(a, b);
    return *(const uint*)&hv;
}
// m16n8k16 fp16 mma, fp32 accumulate. Same mantissa width as tf32, 2x rate.
__device__ __forceinline__ void mma_f16(float* d, uint a0, uint a1, uint a2, uint a3,
                                        uint b0, uint b1) {
    asm("mma.sync.aligned.m16n8k16.row.col.f32.f16.f16.f32 "
        "{%0,%1,%2,%3},{%4,%5,%6,%7},{%8,%9},{%0,%1,%2,%3};"
        : "+f"(d[0]), "+f"(d[1]), "+f"(d[2]), "+f"(d[3])
        : "r"(a0), "r"(a1), "r"(a2), "r"(a3), "r"(b0), "r"(b1));
}

#define CONV_BLOCKS (BB * 24 * KCH)   // 768
#define TR_BLOCKS   1152              // 3 x 96 x 4
#define ZERO_BLOCKS 32
#define TOTAL_A     (CONV_BLOCKS + TR_BLOCKS + ZERO_BLOCKS)
#define XS_CSTRIDE  600               // per PAIR-plane stride (uints); %32=24 -> conflict-free
#define XS_RSTRIDE  100

// halo cells per batch: top 98 + bottom 98 + left 96 + right 96 = 388
#define HALO_CELLS  388
#define HALO_TOTAL  (BB * HALO_CELLS * 64)   // float2 entries

// ============================================================================
// Fused kernel A: fp16-mma conv split-K (0..767) + transpose (768..1919)
//                 + halo-zero (1920..1951).   [UNCHANGED from R11 — protected]
// ============================================================================
__global__ __launch_bounds__(256, 2)
void fusedA_kernel(const float* __restrict__ x, const float* __restrict__ rw)
{
    __shared__ union {
        struct {
            uint xs[8 * XS_CSTRIDE];  // 8 ch-pairs x (6 rows x 98 cols) half2
            uint ws[9 * 8 * 24];      // [tap][ch-pair][out] half2
        } cv;
        float2 tr[64][33];
    } sm;

    const int tid = threadIdx.x;
    const int bi  = blockIdx.x;

    if (bi >= CONV_BLOCKS + TR_BLOCKS) {
        // -------------------- HALO-ZERO role --------------------
        const int zi = bi - (CONV_BLOCKS + TR_BLOCKS);
        for (int i = zi * 256 + tid; i < HALO_TOTAL; i += ZERO_BLOCKS * 256) {
            int b = i / (HALO_CELLS * 64);
            int r = i - b * (HALO_CELLS * 64);
            int cell = r >> 6, cp = r & 63;
            int hh, ww;
            if (cell < 98)       { hh = -1; ww = cell - 1; }
            else if (cell < 196) { hh = 96; ww = cell - 98 - 1; }
            else if (cell < 292) { hh = cell - 196; ww = -1; }
            else                 { hh = cell - 292; ww = 96; }
            g_xt[(((size_t)b * HP + (hh + 1)) * WP + (ww + 1)) * 64 + cp] =
                make_float2(0.0f, 0.0f);
        }
        return;
    }

    if (bi >= CONV_BLOCKS) {
        // -------------------- TRANSPOSE role --------------------
        const int ti = bi - CONV_BLOCKS;             // 0..1151 = 3 x 96 x 4
        const int w0 = (ti % 3) * 32;
        const int h  = (ti / 3) % 96;
        const int b  = ti / 288;
        const int tx = tid & 31, ty = tid >> 5;      // ty 0..7

        const float* xb = x + ((size_t)b * CC) * HWP + h * WW + w0;
        #pragma unroll
        for (int k = 0; k < 8; k++) {
            int c = ty + 8 * k;                      // 0..63
            float v0 = xb[(size_t)c * HWP + tx];
            float v1 = xb[(size_t)(c + 64) * HWP + tx];
            sm.tr[c][tx] = make_float2(v0, v1);
        }
        __syncthreads();
        float2* ob = g_xt + (((size_t)b * HP + (h + 1)) * WP + (w0 + 1)) * 64;
        #pragma unroll
        for (int k = 0; k < 8; k++) {
            int cp = tx + 32 * (k & 1);
            int wl = ty + 8 * (k >> 1);
            ob[(size_t)wl * 64 + cp] = sm.tr[cp][wl];
        }
        return;
    }

    // -------------------- CONV role --------------------
    const int lane = tid & 31;
    const int warp = tid >> 5;        // 0..7
    const int g  = lane >> 2;         // groupID 0..7 (pixel row within m16)
    const int tg = lane & 3;          // threadID-in-group 0..3 (k selector)

    const int b     = bi / (24 * KCH);
    const int rest  = bi % (24 * KCH);
    const int h0    = (rest % 24) * 4;     // 4 image rows per block
    const int chunk = rest / 24;           // 0..7

    float D[3][3][4];
    #pragma unroll
    for (int i = 0; i < 3; i++)
        #pragma unroll
        for (int j = 0; j < 3; j++)
            #pragma unroll
            for (int k = 0; k < 4; k++) D[i][j][k] = 0.0f;

    // ---- stage x as channel-paired half2: warp = pair (ch 2w, 2w+1). NO div.
    {
        const float* xg0 = x + ((size_t)(b * CC + chunk * 16 + 2 * warp)) * HWP;
        const float* xg1 = xg0 + HWP;
        uint* xrow = sm.cv.xs + warp * XS_CSTRIDE;
        #pragma unroll
        for (int rr = 0; rr < 6; rr++) {
            const int grow = h0 - 1 + rr;
            const bool rok = (unsigned)grow < (unsigned)HH;
            const float* xr0 = xg0 + grow * WW;
            const float* xr1 = xg1 + grow * WW;
            #pragma unroll
            for (int q = 0; q < 4; q++) {
                const int cc = q * 32 + lane;
                if (cc < 98) {
                    const int gcol = cc - 1;
                    const bool ok = rok && (unsigned)gcol < (unsigned)WW;
                    float v0 = ok ? xr0[gcol] : 0.0f;
                    float v1 = ok ? xr1[gcol] : 0.0f;
                    xrow[rr * XS_RSTRIDE + cc] = packh2(v0, v1);
                }
            }
        }
    }
    // ---- stage w: ws[t][pair][o] = half2(w[2kp], w[2kp+1]) (o>=18 zero) ----
    for (int i = tid; i < 1728; i += 256) {
        int t = i / 192, rem = i - t * 192;
        int kp = rem / 24, o = rem - kp * 24;
        const int c0 = chunk * 16 + 2 * kp;
        float v0 = 0.0f, v1 = 0.0f;
        if (o < OC) {
            v0 = rw[((size_t)o * CC + c0) * 9 + t];
            v1 = rw[((size_t)o * CC + c0 + 1) * 9 + t];
        }
        sm.cv.ws[i] = packh2(v0, v1);
    }
    __syncthreads();

    #pragma unroll
    for (int kk = 0; kk < 9; kk++) {          // tap = kk ; k16 = all 16 channels
        const int dr = kk / 3, dc = kk % 3;
        uint b0[3], b1[3];
        #pragma unroll
        for (int nt = 0; nt < 3; nt++) {
            b0[nt] = sm.cv.ws[kk * 192 + tg * 24 + nt * 8 + g];
            b1[nt] = sm.cv.ws[kk * 192 + (tg + 4) * 24 + nt * 8 + g];
        }
        #pragma unroll
        for (int mt = 0; mt < 3; mt++) {
            const int m  = warp + mt * 8;      // m16-tile 0..23
            const int r  = m / 6;              // row 0..3 within block
            const int cb = (m % 6) * 16;       // col base
            const int base = (r + dr) * XS_RSTRIDE + cb + dc + g;
            uint a0 = sm.cv.xs[tg * XS_CSTRIDE + base];
            uint a1 = sm.cv.xs[tg * XS_CSTRIDE + base + 8];
            uint a2 = sm.cv.xs[(tg + 4) * XS_CSTRIDE + base];
            uint a3 = sm.cv.xs[(tg + 4) * XS_CSTRIDE + base + 8];
            #pragma unroll
            for (int nt = 0; nt < 3; nt++)
                mma_f16(D[mt][nt], a0, a1, a2, a3, b0[nt], b1[nt]);
        }
    }

    // ---- epilogue: write raw coordinate partial sums ----
    float* rp = g_rotp + (size_t)(chunk * BB + b) * OC * HWP;
    #pragma unroll
    for (int mt = 0; mt < 3; mt++) {
        const int m  = warp + mt * 8;
        const int r  = m / 6;
        const int cb = (m % 6) * 16;
        const int pl = (h0 + r) * WW + cb + g;     // pixel offset within image
        #pragma unroll
        for (int nt = 0; nt < 3; nt++) {
            const int t = nt * 4 + tg;
            if (t > 8) continue;
            #pragma unroll
            for (int half = 0; half < 2; half++) {
                rp[(size_t)(2 * t)     * HWP + pl + half * 8] = D[mt][nt][2 * half];
                rp[(size_t)(2 * t + 1) * HWP + pl + half * 8] = D[mt][nt][2 * half + 1];
            }
        }
    }
}

// ============================================================================
// Kernel 2: fused coef + deform gather (R10 gather form — best measured) with
// forced 5 CTAs/SM occupancy (latency-bound at 4; regs capped to ~51).
// fp16 weight table, fp32 arithmetic. Block = 256: cp(64) x pg(4).
// ============================================================================
__global__ __launch_bounds__(256, 5)
void deform_kernel(const float* __restrict__ wt, const float* __restrict__ rb,
                   float* __restrict__ out)
{
    __shared__ uint   wt2h[16][64];  // half2{w[cp], w[cp+64]} per slot  (4 KB)
    __shared__ float4 cfa[9][32];    // {c00,c00,c01,c01}
    __shared__ float4 cfb[9][32];    // {c10,c10,c11,c11}
    __shared__ uint   ids[9][32];
    __shared__ float  resL[64][33];
    __shared__ float  resH[64][33];

    const int tid = threadIdx.x;
    const int cp = tid & 63;            // channel pair lane
    const int pg = tid >> 6;            // pixel group 0..3 -> pixels 8pg..8pg+7
    const int w0 = blockIdx.x * 32;
    const int h  = blockIdx.y;
    const int b  = blockIdx.z;
    const int px0 = pg * 8;

    // stage channel-paired fp16 weight table
    for (int i = tid; i < 16 * 64; i += 256) {
        int s = i >> 6, c = i & 63;
        wt2h[s][c] = packh2(wt[c * 16 + s], wt[(c + 64) * 16 + s]);
    }

    // fused coef: items (t 0..8, p 0..31) = 288 ; sum KCH partials + bias
    for (int i = tid; i < 288; i += 256) {
        int t = i >> 5, p = i & 31;
        int off = h * WW + w0 + p;
        int o0 = 2 * t, o1 = 2 * t + 1;
        float chv = rb[o0] + 0.5f + (float)(t / 3);
        float cwv = rb[o1] + 0.5f + (float)(t % 3);
        #pragma unroll
        for (int ch = 0; ch < KCH; ch++) {
            const float* base = g_rotp + ((size_t)(ch * BB + b) * OC) * HWP + off;
            chv += base[(size_t)o0 * HWP];
            cwv += base[(size_t)o1 * HWP];
        }
        chv = fminf(fmaxf(chv, 0.0f), 3.0f);
        cwv = fminf(fmaxf(cwv, 0.0f), 3.0f);
        float h0f = floorf(chv), w0f = floorf(cwv);
        float lh = chv - h0f, lw = cwv - w0f;
        int h0i = (int)h0f, w0i = (int)w0f;
        int h1i = min(h0i + 1, 3), w1i = min(w0i + 1, 3);
        float c00 = (1.0f - lh) * (1.0f - lw);
        float c01 = (1.0f - lh) * lw;
        float c10 = lh * (1.0f - lw);
        float c11 = lh * lw;
        cfa[t][p] = make_float4(c00, c00, c01, c01);
        cfb[t][p] = make_float4(c10, c10, c11, c11);
        ids[t][p] = (uint)(h0i * 4 + w0i)
                  | ((uint)(h0i * 4 + w1i) << 8)
                  | ((uint)(h1i * 4 + w0i) << 16)
                  | ((uint)(h1i * 4 + w1i) << 24);
    }
    __syncthreads();

    // row base pointers into the padded tensor (loop-invariant, no predicates)
    const float2* xrow0 = g_xt + (((size_t)b * HP + h)     * WP) * 64 + cp;  // h-1
    const float2* xrow1 = g_xt + (((size_t)b * HP + h + 1) * WP) * 64 + cp;  // h
    const float2* xrow2 = g_xt + (((size_t)b * HP + h + 2) * WP) * 64 + cp;  // h+1

    ull xv[3][4];
    #pragma unroll
    for (int dj = 0; dj < 2; dj++) {
        const int pc = (w0 + px0 + dj) * 64;       // padded col
        xv[0][dj] = *(const ull*)(xrow0 + pc);
        xv[1][dj] = *(const ull*)(xrow1 + pc);
        xv[2][dj] = *(const ull*)(xrow2 + pc);
    }

    #pragma unroll
    for (int pp = 0; pp < 4; pp++) {
        const int p0 = px0 + 2 * pp;
        #pragma unroll
        for (int dj = 2; dj < 4; dj++) {
            const int pc = (w0 + p0 + dj) * 64;
            xv[0][dj] = *(const ull*)(xrow0 + pc);
            xv[1][dj] = *(const ull*)(xrow1 + pc);
            xv[2][dj] = *(const ull*)(xrow2 + pc);
        }

        ull accA0 = 0ull, accA1 = 0ull, accB0 = 0ull, accB1 = 0ull;
        #pragma unroll
        for (int t = 0; t < 9; t++) {
            const int tr = t / 3, tc = t % 3;
            { // pixel A
                const ulonglong2 ca = *(const ulonglong2*)&cfa[t][p0];
                const ulonglong2 cb = *(const ulonglong2*)&cfb[t][p0];
                const uint ox = ids[t][p0];
                ull g00 = h2tof2(wt2h[ ox        & 15u][cp]);
                ull g01 = h2tof2(wt2h[(ox >> 8)  & 15u][cp]);
                ull g10 = h2tof2(wt2h[(ox >> 16) & 15u][cp]);
                ull g11 = h2tof2(wt2h[(ox >> 24) & 15u][cp]);
                ull s0 = mul2(ca.x, g00); fma2(s0, ca.y, g01);
                ull s1 = mul2(cb.x, g10); fma2(s1, cb.y, g11);
                fma2(accA0, s0, xv[tr][tc]);
                fma2(accA1, s1, xv[tr][tc]);
            }
            { // pixel B
                const ulonglong2 ca = *(const ulonglong2*)&cfa[t][p0 + 1];
                const ulonglong2 cb = *(const ulonglong2*)&cfb[t][p0 + 1];
                const uint ox = ids[t][p0 + 1];
                ull g00 = h2tof2(wt2h[ ox        & 15u][cp]);
                ull g01 = h2tof2(wt2h[(ox >> 8)  & 15u][cp]);
                ull g10 = h2tof2(wt2h[(ox >> 16) & 15u][cp]);
                ull g11 = h2tof2(wt2h[(ox >> 24) & 15u][cp]);
                ull s0 = mul2(ca.x, g00); fma2(s0, ca.y, g01);
                ull s1 = mul2(cb.x, g10); fma2(s1, cb.y, g11);
                fma2(accB0, s0, xv[tr][tc + 1]);
                fma2(accB1, s1, xv[tr][tc + 1]);
            }
        }

        float aL, aH, bL, bH;
        unpackf2(add2(accA0, accA1), aL, aH);
        unpackf2(add2(accB0, accB1), bL, bH);
        resL[cp][p0]     = aL; resH[cp][p0]     = aH;
        resL[cp][p0 + 1] = bL; resH[cp][p0 + 1] = bH;

        #pragma unroll
        for (int di = 0; di < 3; di++) { xv[di][0] = xv[di][2]; xv[di][1] = xv[di][3]; }
    }
    __syncthreads();

    // coalesced NCHW write: 128 ch x 32 px
    float* ob = out + (size_t)b * CC * HWP + h * WW + w0;
    #pragma unroll
    for (int i = tid; i < 128 * 32; i += 256) {
        int c = i >> 5, p = i & 31;
        float v = (c < 64) ? resL[c][p] : resH[c - 64][p];
        ob[(size_t)c * HWP + p] = v;
    }
}

// ============================================================================
extern "C" void kernel_launch(void* const* d_in, const int* in_sizes, int n_in,
                              void* d_out, int out_size)
{
    const float* x  = (const float*)d_in[0];   // [4,128,96,96]
    const float* rw = (const float*)d_in[1];   // [18,128,3,3]
    const float* rb = (const float*)d_in[2];   // [18]
    const float* wt = (const float*)d_in[3];   // [128,4,4]
    float* out = (float*)d_out;                // [4,128,96,96]

    fusedA_kernel<<<TOTAL_A, 256>>>(x, rw);
    deform_kernel<<<dim3(3, HH, BB), 256>>>(wt, rb, out);
}

// round 13
// speedup vs baseline: 1.1611x; 1.1611x over previous
#include <cuda_runtime.h>
#include <cuda_fp16.h>
#include <cstdint>

typedef unsigned long long ull;
typedef unsigned int uint;

// Problem constants
#define BB   4
#define CC   128
#define HH   96
#define WW   96
#define OC   18          // G*K*K*2
#define HWP  (HH*WW)     // 9216
#define NPIX (BB*HWP)    // 36864
#define KCH  8           // split-K chunks for conv (16 channels each)
#define HP   98          // padded H (halo)
#define WP   98          // padded W (halo)

// ---------------- scratch (static device arrays; no allocation) ----------------
__device__ float g_rotp[KCH * BB * OC * HWP];            // conv partial coord sums
__device__ uint  g_xt[(size_t)BB * HP * WP * 64];        // padded NHWC ch-paired fp16:
                                                         // [b][h][w][cp] = h2(x[cp],x[cp+64])

// ---------------- helpers ----------------
__device__ __forceinline__ void unpackf2(ull v, float& a, float& b) {
    asm("mov.b64 {%0, %1}, %2;" : "=f"(a), "=f"(b) : "l"(v));
}
__device__ __forceinline__ void fma2(ull& d, ull a, ull b) {
    asm("fma.rn.f32x2 %0, %1, %2, %0;" : "+l"(d) : "l"(a), "l"(b));
}
__device__ __forceinline__ ull add2(ull a, ull b) {
    ull r; asm("add.rn.f32x2 %0, %1, %2;" : "=l"(r) : "l"(a), "l"(b)); return r;
}
// fp16-pair -> packed f32x2 (storage-only quantization; accumulate stays fp32)
__device__ __forceinline__ ull h2tof2(uint raw) {
    float2 f = __half22float2(*(const __half2*)&raw);
    return *(const ull*)&f;
}
__device__ __forceinline__ uint packh2(float a, float b) {
    __half2 hv = __floats2half2_rn(a, b);
    return *(const uint*)&hv;
}
__device__ __forceinline__ __half2 u2h(uint v) { return *(const __half2*)&v; }
__device__ __forceinline__ uint h2u(__half2 v) { return *(const uint*)&v; }
// m16n8k16 fp16 mma, fp32 accumulate. Same mantissa width as tf32, 2x rate.
__device__ __forceinline__ void mma_f16(float* d, uint a0, uint a1, uint a2, uint a3,
                                        uint b0, uint b1) {
    asm("mma.sync.aligned.m16n8k16.row.col.f32.f16.f16.f32 "
        "{%0,%1,%2,%3},{%4,%5,%6,%7},{%8,%9},{%0,%1,%2,%3};"
        : "+f"(d[0]), "+f"(d[1]), "+f"(d[2]), "+f"(d[3])
        : "r"(a0), "r"(a1), "r"(a2), "r"(a3), "r"(b0), "r"(b1));
}
// fp16 bilinear blend: cf01 = h2(c00,c01), cf23 = h2(c10,c11); q0={g00,g01}, q1={g10,g11}
// (each g = channel-paired half2). Coefs duplicated in-register via PRMT.
__device__ __forceinline__ uint hblend(uint cf01, uint cf23, uint2 q0, uint2 q1) {
    __half2 c00 = u2h(__byte_perm(cf01, 0, 0x1010));
    __half2 c01 = u2h(__byte_perm(cf01, 0, 0x3232));
    __half2 c10 = u2h(__byte_perm(cf23, 0, 0x1010));
    __half2 c11 = u2h(__byte_perm(cf23, 0, 0x3232));
    __half2 s = __hmul2(c00, u2h(q0.x));
    s = __hfma2(c01, u2h(q0.y), s);
    s = __hfma2(c10, u2h(q1.x), s);
    s = __hfma2(c11, u2h(q1.y), s);
    return h2u(s);
}

#define CONV_BLOCKS (BB * 24 * KCH)   // 768
#define TR_BLOCKS   1152              // 3 x 96 x 4
#define ZERO_BLOCKS 32
#define TOTAL_A     (CONV_BLOCKS + TR_BLOCKS + ZERO_BLOCKS)
#define XS_CSTRIDE  600               // per PAIR-plane stride (uints); %32=24 -> conflict-free
#define XS_RSTRIDE  100

// halo cells per batch: top 98 + bottom 98 + left 96 + right 96 = 388
#define HALO_CELLS  388
#define HALO_TOTAL  (BB * HALO_CELLS * 64)   // uint entries

// ============================================================================
// Fused kernel A: fp16-mma conv split-K (0..767) + transpose (768..1919)
//                 + halo-zero (1920..1951). Conv path unchanged (protected);
//                 transpose now packs x to fp16 half2 (half the write bytes).
// ============================================================================
__global__ __launch_bounds__(256, 2)
void fusedA_kernel(const float* __restrict__ x, const float* __restrict__ rw)
{
    __shared__ union {
        struct {
            uint xs[8 * XS_CSTRIDE];  // 8 ch-pairs x (6 rows x 98 cols) half2
            uint ws[9 * 8 * 24];      // [tap][ch-pair][out] half2
        } cv;
        uint tr[64][33];
    } sm;

    const int tid = threadIdx.x;
    const int bi  = blockIdx.x;

    if (bi >= CONV_BLOCKS + TR_BLOCKS) {
        // -------------------- HALO-ZERO role --------------------
        const int zi = bi - (CONV_BLOCKS + TR_BLOCKS);
        for (int i = zi * 256 + tid; i < HALO_TOTAL; i += ZERO_BLOCKS * 256) {
            int b = i / (HALO_CELLS * 64);
            int r = i - b * (HALO_CELLS * 64);
            int cell = r >> 6, cp = r & 63;
            int hh, ww;
            if (cell < 98)       { hh = -1; ww = cell - 1; }
            else if (cell < 196) { hh = 96; ww = cell - 98 - 1; }
            else if (cell < 292) { hh = cell - 196; ww = -1; }
            else                 { hh = cell - 292; ww = 96; }
            g_xt[(((size_t)b * HP + (hh + 1)) * WP + (ww + 1)) * 64 + cp] = 0u;
        }
        return;
    }

    if (bi >= CONV_BLOCKS) {
        // -------------------- TRANSPOSE role (fp16 pack) --------------------
        const int ti = bi - CONV_BLOCKS;             // 0..1151 = 3 x 96 x 4
        const int w0 = (ti % 3) * 32;
        const int h  = (ti / 3) % 96;
        const int b  = ti / 288;
        const int tx = tid & 31, ty = tid >> 5;      // ty 0..7

        const float* xb = x + ((size_t)b * CC) * HWP + h * WW + w0;
        #pragma unroll
        for (int k = 0; k < 8; k++) {
            int c = ty + 8 * k;                      // 0..63
            float v0 = xb[(size_t)c * HWP + tx];
            float v1 = xb[(size_t)(c + 64) * HWP + tx];
            sm.tr[c][tx] = packh2(v0, v1);
        }
        __syncthreads();
        uint* ob = g_xt + (((size_t)b * HP + (h + 1)) * WP + (w0 + 1)) * 64;
        #pragma unroll
        for (int k = 0; k < 8; k++) {
            int cp = tx + 32 * (k & 1);
            int wl = ty + 8 * (k >> 1);
            ob[(size_t)wl * 64 + cp] = sm.tr[cp][wl];
        }
        return;
    }

    // -------------------- CONV role (unchanged from R11/R12) --------------------
    const int lane = tid & 31;
    const int warp = tid >> 5;        // 0..7
    const int g  = lane >> 2;         // groupID 0..7 (pixel row within m16)
    const int tg = lane & 3;          // threadID-in-group 0..3 (k selector)

    const int b     = bi / (24 * KCH);
    const int rest  = bi % (24 * KCH);
    const int h0    = (rest % 24) * 4;     // 4 image rows per block
    const int chunk = rest / 24;           // 0..7

    float D[3][3][4];
    #pragma unroll
    for (int i = 0; i < 3; i++)
        #pragma unroll
        for (int j = 0; j < 3; j++)
            #pragma unroll
            for (int k = 0; k < 4; k++) D[i][j][k] = 0.0f;

    // ---- stage x as channel-paired half2: warp = pair (ch 2w, 2w+1). NO div.
    {
        const float* xg0 = x + ((size_t)(b * CC + chunk * 16 + 2 * warp)) * HWP;
        const float* xg1 = xg0 + HWP;
        uint* xrow = sm.cv.xs + warp * XS_CSTRIDE;
        #pragma unroll
        for (int rr = 0; rr < 6; rr++) {
            const int grow = h0 - 1 + rr;
            const bool rok = (unsigned)grow < (unsigned)HH;
            const float* xr0 = xg0 + grow * WW;
            const float* xr1 = xg1 + grow * WW;
            #pragma unroll
            for (int q = 0; q < 4; q++) {
                const int cc = q * 32 + lane;
                if (cc < 98) {
                    const int gcol = cc - 1;
                    const bool ok = rok && (unsigned)gcol < (unsigned)WW;
                    float v0 = ok ? xr0[gcol] : 0.0f;
                    float v1 = ok ? xr1[gcol] : 0.0f;
                    xrow[rr * XS_RSTRIDE + cc] = packh2(v0, v1);
                }
            }
        }
    }
    // ---- stage w: ws[t][pair][o] = half2(w[2kp], w[2kp+1]) (o>=18 zero) ----
    for (int i = tid; i < 1728; i += 256) {
        int t = i / 192, rem = i - t * 192;
        int kp = rem / 24, o = rem - kp * 24;
        const int c0 = chunk * 16 + 2 * kp;
        float v0 = 0.0f, v1 = 0.0f;
        if (o < OC) {
            v0 = rw[((size_t)o * CC + c0) * 9 + t];
            v1 = rw[((size_t)o * CC + c0 + 1) * 9 + t];
        }
        sm.cv.ws[i] = packh2(v0, v1);
    }
    __syncthreads();

    #pragma unroll
    for (int kk = 0; kk < 9; kk++) {          // tap = kk ; k16 = all 16 channels
        const int dr = kk / 3, dc = kk % 3;
        uint b0[3], b1[3];
        #pragma unroll
        for (int nt = 0; nt < 3; nt++) {
            b0[nt] = sm.cv.ws[kk * 192 + tg * 24 + nt * 8 + g];
            b1[nt] = sm.cv.ws[kk * 192 + (tg + 4) * 24 + nt * 8 + g];
        }
        #pragma unroll
        for (int mt = 0; mt < 3; mt++) {
            const int m  = warp + mt * 8;      // m16-tile 0..23
            const int r  = m / 6;              // row 0..3 within block
            const int cb = (m % 6) * 16;       // col base
            const int base = (r + dr) * XS_RSTRIDE + cb + dc + g;
            uint a0 = sm.cv.xs[tg * XS_CSTRIDE + base];
            uint a1 = sm.cv.xs[tg * XS_CSTRIDE + base + 8];
            uint a2 = sm.cv.xs[(tg + 4) * XS_CSTRIDE + base];
            uint a3 = sm.cv.xs[(tg + 4) * XS_CSTRIDE + base + 8];
            #pragma unroll
            for (int nt = 0; nt < 3; nt++)
                mma_f16(D[mt][nt], a0, a1, a2, a3, b0[nt], b1[nt]);
        }
    }

    // ---- epilogue: write raw coordinate partial sums ----
    float* rp = g_rotp + (size_t)(chunk * BB + b) * OC * HWP;
    #pragma unroll
    for (int mt = 0; mt < 3; mt++) {
        const int m  = warp + mt * 8;
        const int r  = m / 6;
        const int cb = (m % 6) * 16;
        const int pl = (h0 + r) * WW + cb + g;     // pixel offset within image
        #pragma unroll
        for (int nt = 0; nt < 3; nt++) {
            const int t = nt * 4 + tg;
            if (t > 8) continue;
            #pragma unroll
            for (int half = 0; half < 2; half++) {
                rp[(size_t)(2 * t)     * HWP + pl + half * 8] = D[mt][nt][2 * half];
                rp[(size_t)(2 * t + 1) * HWP + pl + half * 8] = D[mt][nt][2 * half + 1];
            }
        }
    }
}

// ============================================================================
// Kernel 2: fused coef + deform gather — WAVEFRONT-MINIMIZED.
//  - coef+id packed into ONE uniform LDS.128 per (tap,pixel)  (6 wf -> 2 /tap-pair)
//  - fp16 quad weight table, single pre-scaled index (1 IADD + 2 LDS.64)
//  - fp16 blend (PRMT-dup coefs, HMUL2/HFMA2), fp32 accumulate
//  - x loaded from fp16 g_xt (half the LDG bytes), cvt once per load
// Block = 256 threads: cp(64) x pg(4). Tile = 1 row x 32 px x 128 ch.
// ============================================================================
__global__ __launch_bounds__(256)
void deform_kernel(const float* __restrict__ wt, const float* __restrict__ rb,
                   float* __restrict__ out)
{
    __shared__ uint2 wtq[20][64];    // {h2(wL[s],wH[s]), h2(wL[s+1],wH[s+1])} (10 KB)
    __shared__ uint4 cfid[9][32];    // {h2(c00,c01), h2(c10,c11), quad_byte_off, 0}
    __shared__ float resL[64][33];
    __shared__ float resH[64][33];

    const int tid = threadIdx.x;
    const int cp = tid & 63;            // channel pair lane
    const int pg = tid >> 6;            // pixel group 0..3 -> pixels 8pg..8pg+7
    const int w0 = blockIdx.x * 32;
    const int h  = blockIdx.y;
    const int b  = blockIdx.z;
    const int px0 = pg * 8;

    // stage fp16 quad weight table (rows 16..19 zero-padded)
    for (int i = tid; i < 20 * 64; i += 256) {
        int s = i >> 6, c = i & 63;
        float wl0 = (s < 16)     ? wt[c * 16 + s]            : 0.0f;
        float wh0 = (s < 16)     ? wt[(c + 64) * 16 + s]     : 0.0f;
        float wl1 = (s + 1 < 16) ? wt[c * 16 + s + 1]        : 0.0f;
        float wh1 = (s + 1 < 16) ? wt[(c + 64) * 16 + s + 1] : 0.0f;
        wtq[s][c] = make_uint2(packh2(wl0, wh0), packh2(wl1, wh1));
    }

    // fused coef: items (t 0..8, p 0..31) = 288 ; sum KCH partials + bias
    for (int i = tid; i < 288; i += 256) {
        int t = i >> 5, p = i & 31;
        int off = h * WW + w0 + p;
        int o0 = 2 * t, o1 = 2 * t + 1;
        float chv = rb[o0] + 0.5f + (float)(t / 3);
        float cwv = rb[o1] + 0.5f + (float)(t % 3);
        #pragma unroll
        for (int ch = 0; ch < KCH; ch++) {
            const float* base = g_rotp + ((size_t)(ch * BB + b) * OC) * HWP + off;
            chv += base[(size_t)o0 * HWP];
            cwv += base[(size_t)o1 * HWP];
        }
        chv = fminf(fmaxf(chv, 0.0f), 3.0f);
        cwv = fminf(fmaxf(cwv, 0.0f), 3.0f);
        float h0f = floorf(chv), w0f = floorf(cwv);
        float lh = chv - h0f, lw = cwv - w0f;
        int h0i = (int)h0f, w0i = (int)w0f;
        float c00 = (1.0f - lh) * (1.0f - lw);
        float c01 = (1.0f - lh) * lw;
        float c10 = lh * (1.0f - lw);
        float c11 = lh * lw;
        cfid[t][p] = make_uint4(packh2(c00, c01), packh2(c10, c11),
                                (uint)(h0i * 4 + w0i) << 9, 0u);
    }
    __syncthreads();

    // row base pointers into the padded fp16 tensor (loop-invariant)
    const uint* xrow0 = g_xt + (((size_t)b * HP + h)     * WP) * 64 + cp;  // h-1
    const uint* xrow1 = g_xt + (((size_t)b * HP + h + 1) * WP) * 64 + cp;  // h
    const uint* xrow2 = g_xt + (((size_t)b * HP + h + 2) * WP) * 64 + cp;  // h+1
    const char* wbase = (const char*)&wtq[0][cp];

    ull xv[3][4];   // f32x2 (converted at load)
    #pragma unroll
    for (int dj = 0; dj < 2; dj++) {
        const int pc = (w0 + px0 + dj) * 64;       // padded col
        xv[0][dj] = h2tof2(xrow0[pc]);
        xv[1][dj] = h2tof2(xrow1[pc]);
        xv[2][dj] = h2tof2(xrow2[pc]);
    }

    #pragma unroll
    for (int pp = 0; pp < 4; pp++) {
        const int p0 = px0 + 2 * pp;
        #pragma unroll
        for (int dj = 2; dj < 4; dj++) {
            const int pc = (w0 + p0 + dj) * 64;
            xv[0][dj] = h2tof2(xrow0[pc]);
            xv[1][dj] = h2tof2(xrow1[pc]);
            xv[2][dj] = h2tof2(xrow2[pc]);
        }

        ull accA = 0ull, accB = 0ull;
        #pragma unroll
        for (int t = 0; t < 9; t++) {
            const int tr = t / 3, tc = t % 3;
            { // pixel A
                const uint4 cf = cfid[t][p0];                       // 1 uniform LDS.128
                const uint2 q0 = *(const uint2*)(wbase + cf.z);
                const uint2 q1 = *(const uint2*)(wbase + cf.z + 2048);
                uint s = hblend(cf.x, cf.y, q0, q1);
                fma2(accA, h2tof2(s), xv[tr][tc]);
            }
            { // pixel B
                const uint4 cf = cfid[t][p0 + 1];
                const uint2 q0 = *(const uint2*)(wbase + cf.z);
                const uint2 q1 = *(const uint2*)(wbase + cf.z + 2048);
                uint s = hblend(cf.x, cf.y, q0, q1);
                fma2(accB, h2tof2(s), xv[tr][tc + 1]);
            }
        }

        float aL, aH, bL, bH;
        unpackf2(accA, aL, aH);
        unpackf2(accB, bL, bH);
        resL[cp][p0]     = aL; resH[cp][p0]     = aH;
        resL[cp][p0 + 1] = bL; resH[cp][p0 + 1] = bH;

        #pragma unroll
        for (int di = 0; di < 3; di++) { xv[di][0] = xv[di][2]; xv[di][1] = xv[di][3]; }
    }
    __syncthreads();

    // coalesced NCHW write: 128 ch x 32 px
    float* ob = out + (size_t)b * CC * HWP + h * WW + w0;
    #pragma unroll
    for (int i = tid; i < 128 * 32; i += 256) {
        int c = i >> 5, p = i & 31;
        float v = (c < 64) ? resL[c][p] : resH[c - 64][p];
        ob[(size_t)c * HWP + p] = v;
    }
}

// ============================================================================
extern "C" void kernel_launch(void* const* d_in, const int* in_sizes, int n_in,
                              void* d_out, int out_size)
{
    const float* x  = (const float*)d_in[0];   // [4,128,96,96]
    const float* rw = (const float*)d_in[1];   // [18,128,3,3]
    const float* rb = (const float*)d_in[2];   // [18]
    const float* wt = (const float*)d_in[3];   // [128,4,4]
    float* out = (float*)d_out;                // [4,128,96,96]

    fusedA_kernel<<<TOTAL_A, 256>>>(x, rw);
    deform_kernel<<<dim3(3, HH, BB), 256>>>(wt, rb, out);
}

// round 14
// speedup vs baseline: 1.1654x; 1.0037x over previous
#include <cuda_runtime.h>
#include <cuda_fp16.h>
#include <cstdint>

typedef unsigned long long ull;
typedef unsigned int uint;

// Problem constants
#define BB   4
#define CC   128
#define HH   96
#define WW   96
#define OC   18          // G*K*K*2
#define HWP  (HH*WW)     // 9216
#define NPIX (BB*HWP)    // 36864
#define KCH  8           // split-K chunks for conv (16 channels each)
#define HP   98          // padded H (halo)
#define WP   98          // padded W (halo)

// ---------------- scratch (static device arrays; no allocation) ----------------
__device__ float g_rotp[KCH * BB * OC * HWP];            // conv partial coord sums
__device__ uint  g_xt[(size_t)BB * HP * WP * 64];        // padded NHWC ch-paired fp16:
                                                         // [b][h][w][cp] = h2(x[cp],x[cp+64])

// ---------------- helpers ----------------
__device__ __forceinline__ void unpackf2(ull v, float& a, float& b) {
    asm("mov.b64 {%0, %1}, %2;" : "=f"(a), "=f"(b) : "l"(v));
}
__device__ __forceinline__ void fma2(ull& d, ull a, ull b) {
    asm("fma.rn.f32x2 %0, %1, %2, %0;" : "+l"(d) : "l"(a), "l"(b));
}
// fp16-pair -> packed f32x2 (storage-only quantization; accumulate stays fp32)
__device__ __forceinline__ ull h2tof2(uint raw) {
    float2 f = __half22float2(*(const __half2*)&raw);
    return *(const ull*)&f;
}
__device__ __forceinline__ uint packh2(float a, float b) {
    __half2 hv = __floats2half2_rn(a, b);
    return *(const uint*)&hv;
}
__device__ __forceinline__ __half2 u2h(uint v) { return *(const __half2*)&v; }
__device__ __forceinline__ uint h2u(__half2 v) { return *(const uint*)&v; }
// m16n8k16 fp16 mma, fp32 accumulate. Same mantissa width as tf32, 2x rate.
__device__ __forceinline__ void mma_f16(float* d, uint a0, uint a1, uint a2, uint a3,
                                        uint b0, uint b1) {
    asm("mma.sync.aligned.m16n8k16.row.col.f32.f16.f16.f32 "
        "{%0,%1,%2,%3},{%4,%5,%6,%7},{%8,%9},{%0,%1,%2,%3};"
        : "+f"(d[0]), "+f"(d[1]), "+f"(d[2]), "+f"(d[3])
        : "r"(a0), "r"(a1), "r"(a2), "r"(a3), "r"(b0), "r"(b1));
}
// fp16 bilinear blend: cf01 = h2(c00,c01), cf23 = h2(c10,c11); q0={g00,g01}, q1={g10,g11}
// (each g = channel-paired half2). Coefs duplicated in-register via PRMT.
__device__ __forceinline__ uint hblend(uint cf01, uint cf23, uint2 q0, uint2 q1) {
    __half2 c00 = u2h(__byte_perm(cf01, 0, 0x1010));
    __half2 c01 = u2h(__byte_perm(cf01, 0, 0x3232));
    __half2 c10 = u2h(__byte_perm(cf23, 0, 0x1010));
    __half2 c11 = u2h(__byte_perm(cf23, 0, 0x3232));
    __half2 s = __hmul2(c00, u2h(q0.x));
    s = __hfma2(c01, u2h(q0.y), s);
    s = __hfma2(c10, u2h(q1.x), s);
    s = __hfma2(c11, u2h(q1.y), s);
    return h2u(s);
}

#define CONV_BLOCKS (BB * 24 * KCH)   // 768
#define TR_BLOCKS   1152              // 3 x 96 x 4
#define ZERO_BLOCKS 32
#define TOTAL_A     (CONV_BLOCKS + TR_BLOCKS + ZERO_BLOCKS)
#define XS_CSTRIDE  600               // per PAIR-plane stride (uints); %32=24 -> conflict-free
#define XS_RSTRIDE  100

// halo cells per batch: top 98 + bottom 98 + left 96 + right 96 = 388
#define HALO_CELLS  388
#define HALO_TOTAL  (BB * HALO_CELLS * 64)   // uint entries

// ============================================================================
// Fused kernel A: fp16-mma conv split-K (0..767) + transpose (768..1919)
//                 + halo-zero (1920..1951).   [UNCHANGED from R13 — protected]
// ============================================================================
__global__ __launch_bounds__(256, 2)
void fusedA_kernel(const float* __restrict__ x, const float* __restrict__ rw)
{
    __shared__ union {
        struct {
            uint xs[8 * XS_CSTRIDE];  // 8 ch-pairs x (6 rows x 98 cols) half2
            uint ws[9 * 8 * 24];      // [tap][ch-pair][out] half2
        } cv;
        uint tr[64][33];
    } sm;

    const int tid = threadIdx.x;
    const int bi  = blockIdx.x;

    if (bi >= CONV_BLOCKS + TR_BLOCKS) {
        // -------------------- HALO-ZERO role --------------------
        const int zi = bi - (CONV_BLOCKS + TR_BLOCKS);
        for (int i = zi * 256 + tid; i < HALO_TOTAL; i += ZERO_BLOCKS * 256) {
            int b = i / (HALO_CELLS * 64);
            int r = i - b * (HALO_CELLS * 64);
            int cell = r >> 6, cp = r & 63;
            int hh, ww;
            if (cell < 98)       { hh = -1; ww = cell - 1; }
            else if (cell < 196) { hh = 96; ww = cell - 98 - 1; }
            else if (cell < 292) { hh = cell - 196; ww = -1; }
            else                 { hh = cell - 292; ww = 96; }
            g_xt[(((size_t)b * HP + (hh + 1)) * WP + (ww + 1)) * 64 + cp] = 0u;
        }
        return;
    }

    if (bi >= CONV_BLOCKS) {
        // -------------------- TRANSPOSE role (fp16 pack) --------------------
        const int ti = bi - CONV_BLOCKS;             // 0..1151 = 3 x 96 x 4
        const int w0 = (ti % 3) * 32;
        const int h  = (ti / 3) % 96;
        const int b  = ti / 288;
        const int tx = tid & 31, ty = tid >> 5;      // ty 0..7

        const float* xb = x + ((size_t)b * CC) * HWP + h * WW + w0;
        #pragma unroll
        for (int k = 0; k < 8; k++) {
            int c = ty + 8 * k;                      // 0..63
            float v0 = xb[(size_t)c * HWP + tx];
            float v1 = xb[(size_t)(c + 64) * HWP + tx];
            sm.tr[c][tx] = packh2(v0, v1);
        }
        __syncthreads();
        uint* ob = g_xt + (((size_t)b * HP + (h + 1)) * WP + (w0 + 1)) * 64;
        #pragma unroll
        for (int k = 0; k < 8; k++) {
            int cp = tx + 32 * (k & 1);
            int wl = ty + 8 * (k >> 1);
            ob[(size_t)wl * 64 + cp] = sm.tr[cp][wl];
        }
        return;
    }

    // -------------------- CONV role --------------------
    const int lane = tid & 31;
    const int warp = tid >> 5;        // 0..7
    const int g  = lane >> 2;         // groupID 0..7 (pixel row within m16)
    const int tg = lane & 3;          // threadID-in-group 0..3 (k selector)

    const int b     = bi / (24 * KCH);
    const int rest  = bi % (24 * KCH);
    const int h0    = (rest % 24) * 4;     // 4 image rows per block
    const int chunk = rest / 24;           // 0..7

    float D[3][3][4];
    #pragma unroll
    for (int i = 0; i < 3; i++)
        #pragma unroll
        for (int j = 0; j < 3; j++)
            #pragma unroll
            for (int k = 0; k < 4; k++) D[i][j][k] = 0.0f;

    // ---- stage x as channel-paired half2: warp = pair (ch 2w, 2w+1). NO div.
    {
        const float* xg0 = x + ((size_t)(b * CC + chunk * 16 + 2 * warp)) * HWP;
        const float* xg1 = xg0 + HWP;
        uint* xrow = sm.cv.xs + warp * XS_CSTRIDE;
        #pragma unroll
        for (int rr = 0; rr < 6; rr++) {
            const int grow = h0 - 1 + rr;
            const bool rok = (unsigned)grow < (unsigned)HH;
            const float* xr0 = xg0 + grow * WW;
            const float* xr1 = xg1 + grow * WW;
            #pragma unroll
            for (int q = 0; q < 4; q++) {
                const int cc = q * 32 + lane;
                if (cc < 98) {
                    const int gcol = cc - 1;
                    const bool ok = rok && (unsigned)gcol < (unsigned)WW;
                    float v0 = ok ? xr0[gcol] : 0.0f;
                    float v1 = ok ? xr1[gcol] : 0.0f;
                    xrow[rr * XS_RSTRIDE + cc] = packh2(v0, v1);
                }
            }
        }
    }
    // ---- stage w: ws[t][pair][o] = half2(w[2kp], w[2kp+1]) (o>=18 zero) ----
    for (int i = tid; i < 1728; i += 256) {
        int t = i / 192, rem = i - t * 192;
        int kp = rem / 24, o = rem - kp * 24;
        const int c0 = chunk * 16 + 2 * kp;
        float v0 = 0.0f, v1 = 0.0f;
        if (o < OC) {
            v0 = rw[((size_t)o * CC + c0) * 9 + t];
            v1 = rw[((size_t)o * CC + c0 + 1) * 9 + t];
        }
        sm.cv.ws[i] = packh2(v0, v1);
    }
    __syncthreads();

    #pragma unroll
    for (int kk = 0; kk < 9; kk++) {          // tap = kk ; k16 = all 16 channels
        const int dr = kk / 3, dc = kk % 3;
        uint b0[3], b1[3];
        #pragma unroll
        for (int nt = 0; nt < 3; nt++) {
            b0[nt] = sm.cv.ws[kk * 192 + tg * 24 + nt * 8 + g];
            b1[nt] = sm.cv.ws[kk * 192 + (tg + 4) * 24 + nt * 8 + g];
        }
        #pragma unroll
        for (int mt = 0; mt < 3; mt++) {
            const int m  = warp + mt * 8;      // m16-tile 0..23
            const int r  = m / 6;              // row 0..3 within block
            const int cb = (m % 6) * 16;       // col base
            const int base = (r + dr) * XS_RSTRIDE + cb + dc + g;
            uint a0 = sm.cv.xs[tg * XS_CSTRIDE + base];
            uint a1 = sm.cv.xs[tg * XS_CSTRIDE + base + 8];
            uint a2 = sm.cv.xs[(tg + 4) * XS_CSTRIDE + base];
            uint a3 = sm.cv.xs[(tg + 4) * XS_CSTRIDE + base + 8];
            #pragma unroll
            for (int nt = 0; nt < 3; nt++)
                mma_f16(D[mt][nt], a0, a1, a2, a3, b0[nt], b1[nt]);
        }
    }

    // ---- epilogue: write raw coordinate partial sums ----
    float* rp = g_rotp + (size_t)(chunk * BB + b) * OC * HWP;
    #pragma unroll
    for (int mt = 0; mt < 3; mt++) {
        const int m  = warp + mt * 8;
        const int r  = m / 6;
        const int cb = (m % 6) * 16;
        const int pl = (h0 + r) * WW + cb + g;     // pixel offset within image
        #pragma unroll
        for (int nt = 0; nt < 3; nt++) {
            const int t = nt * 4 + tg;
            if (t > 8) continue;
            #pragma unroll
            for (int half = 0; half < 2; half++) {
                rp[(size_t)(2 * t)     * HWP + pl + half * 8] = D[mt][nt][2 * half];
                rp[(size_t)(2 * t + 1) * HWP + pl + half * 8] = D[mt][nt][2 * half + 1];
            }
        }
    }
}

// ============================================================================
// Kernel 2: fused coef + deform gather — wavefront-minimized + fp16 result
// staging (smem 31.5 -> ~23 KB => 6 CTAs/SM, occ 61% -> 75%; epilogue
// STS/LDS wavefronts halved). Math unchanged: fp16 blend, fp32 accumulate;
// output quantized once to fp16 at staging.
// Block = 256 threads: cp(64) x pg(4). Tile = 1 row x 32 px x 128 ch.
// ============================================================================
__global__ __launch_bounds__(256, 6)
void deform_kernel(const float* __restrict__ wt, const float* __restrict__ rb,
                   float* __restrict__ out)
{
    __shared__ uint2 wtq[20][64];    // {h2(wL[s],wH[s]), h2(wL[s+1],wH[s+1])} (10 KB)
    __shared__ uint4 cfid[9][32];    // {h2(c00,c01), h2(c10,c11), quad_byte_off, 0}
    __shared__ uint  res[64][33];    // h2(out[cp], out[cp+64])  (8.4 KB)

    const int tid = threadIdx.x;
    const int cp = tid & 63;            // channel pair lane
    const int pg = tid >> 6;            // pixel group 0..3 -> pixels 8pg..8pg+7
    const int w0 = blockIdx.x * 32;
    const int h  = blockIdx.y;
    const int b  = blockIdx.z;
    const int px0 = pg * 8;

    // stage fp16 quad weight table (rows 16..19 zero-padded)
    for (int i = tid; i < 20 * 64; i += 256) {
        int s = i >> 6, c = i & 63;
        float wl0 = (s < 16)     ? wt[c * 16 + s]            : 0.0f;
        float wh0 = (s < 16)     ? wt[(c + 64) * 16 + s]     : 0.0f;
        float wl1 = (s + 1 < 16) ? wt[c * 16 + s + 1]        : 0.0f;
        float wh1 = (s + 1 < 16) ? wt[(c + 64) * 16 + s + 1] : 0.0f;
        wtq[s][c] = make_uint2(packh2(wl0, wh0), packh2(wl1, wh1));
    }

    // fused coef: items (t 0..8, p 0..31) = 288 ; sum KCH partials + bias
    for (int i = tid; i < 288; i += 256) {
        int t = i >> 5, p = i & 31;
        int off = h * WW + w0 + p;
        int o0 = 2 * t, o1 = 2 * t + 1;
        float chv = rb[o0] + 0.5f + (float)(t / 3);
        float cwv = rb[o1] + 0.5f + (float)(t % 3);
        #pragma unroll
        for (int ch = 0; ch < KCH; ch++) {
            const float* base = g_rotp + ((size_t)(ch * BB + b) * OC) * HWP + off;
            chv += base[(size_t)o0 * HWP];
            cwv += base[(size_t)o1 * HWP];
        }
        chv = fminf(fmaxf(chv, 0.0f), 3.0f);
        cwv = fminf(fmaxf(cwv, 0.0f), 3.0f);
        float h0f = floorf(chv), w0f = floorf(cwv);
        float lh = chv - h0f, lw = cwv - w0f;
        int h0i = (int)h0f, w0i = (int)w0f;
        float c00 = (1.0f - lh) * (1.0f - lw);
        float c01 = (1.0f - lh) * lw;
        float c10 = lh * (1.0f - lw);
        float c11 = lh * lw;
        cfid[t][p] = make_uint4(packh2(c00, c01), packh2(c10, c11),
                                (uint)(h0i * 4 + w0i) << 9, 0u);
    }
    __syncthreads();

    // row base pointers into the padded fp16 tensor (loop-invariant)
    const uint* xrow0 = g_xt + (((size_t)b * HP + h)     * WP) * 64 + cp;  // h-1
    const uint* xrow1 = g_xt + (((size_t)b * HP + h + 1) * WP) * 64 + cp;  // h
    const uint* xrow2 = g_xt + (((size_t)b * HP + h + 2) * WP) * 64 + cp;  // h+1
    const char* wbase = (const char*)&wtq[0][cp];

    ull xv[3][4];   // f32x2 (converted at load)
    #pragma unroll
    for (int dj = 0; dj < 2; dj++) {
        const int pc = (w0 + px0 + dj) * 64;       // padded col
        xv[0][dj] = h2tof2(xrow0[pc]);
        xv[1][dj] = h2tof2(xrow1[pc]);
        xv[2][dj] = h2tof2(xrow2[pc]);
    }

    #pragma unroll
    for (int pp = 0; pp < 4; pp++) {
        const int p0 = px0 + 2 * pp;
        #pragma unroll
        for (int dj = 2; dj < 4; dj++) {
            const int pc = (w0 + p0 + dj) * 64;
            xv[0][dj] = h2tof2(xrow0[pc]);
            xv[1][dj] = h2tof2(xrow1[pc]);
            xv[2][dj] = h2tof2(xrow2[pc]);
        }

        ull accA = 0ull, accB = 0ull;
        #pragma unroll
        for (int t = 0; t < 9; t++) {
            const int tr = t / 3, tc = t % 3;
            { // pixel A
                const uint4 cf = cfid[t][p0];                       // 1 uniform LDS.128
                const uint2 q0 = *(const uint2*)(wbase + cf.z);
                const uint2 q1 = *(const uint2*)(wbase + cf.z + 2048);
                uint s = hblend(cf.x, cf.y, q0, q1);
                fma2(accA, h2tof2(s), xv[tr][tc]);
            }
            { // pixel B
                const uint4 cf = cfid[t][p0 + 1];
                const uint2 q0 = *(const uint2*)(wbase + cf.z);
                const uint2 q1 = *(const uint2*)(wbase + cf.z + 2048);
                uint s = hblend(cf.x, cf.y, q0, q1);
                fma2(accB, h2tof2(s), xv[tr][tc + 1]);
            }
        }

        float aL, aH, bL, bH;
        unpackf2(accA, aL, aH);
        unpackf2(accB, bL, bH);
        res[cp][p0]     = packh2(aL, aH);
        res[cp][p0 + 1] = packh2(bL, bH);

        #pragma unroll
        for (int di = 0; di < 3; di++) { xv[di][0] = xv[di][2]; xv[di][1] = xv[di][3]; }
    }
    __syncthreads();

    // coalesced NCHW write: each thread writes (cp, p) and (cp+64, p)
    float* ob = out + (size_t)b * CC * HWP + h * WW + w0;
    #pragma unroll
    for (int i = tid; i < 64 * 32; i += 256) {
        int c2 = i >> 5, p = i & 31;
        float lo, hi;
        unpackf2(h2tof2(res[c2][p]), lo, hi);
        ob[(size_t)c2 * HWP + p]        = lo;
        ob[(size_t)(c2 + 64) * HWP + p] = hi;
    }
}

// ============================================================================
extern "C" void kernel_launch(void* const* d_in, const int* in_sizes, int n_in,
                              void* d_out, int out_size)
{
    const float* x  = (const float*)d_in[0];   // [4,128,96,96]
    const float* rw = (const float*)d_in[1];   // [18,128,3,3]
    const float* rb = (const float*)d_in[2];   // [18]
    const float* wt = (const float*)d_in[3];   // [128,4,4]
    float* out = (float*)d_out;                // [4,128,96,96]

    fusedA_kernel<<<TOTAL_A, 256>>>(x, rw);
    deform_kernel<<<dim3(3, HH, BB), 256>>>(wt, rb, out);
}

// round 15
// speedup vs baseline: 1.1877x; 1.0191x over previous
#include <cuda_runtime.h>
#include <cuda_fp16.h>
#include <cstdint>

typedef unsigned long long ull;
typedef unsigned int uint;

// Problem constants
#define BB   4
#define CC   128
#define HH   96
#define WW   96
#define OC   18          // G*K*K*2
#define HWP  (HH*WW)     // 9216
#define NPIX (BB*HWP)    // 36864
#define KCH  4           // split-K chunks for conv (32 channels each, 2 phases)
#define HP   98          // padded H (halo)
#define WP   98          // padded W (halo)

// ---------------- scratch (static device arrays; no allocation) ----------------
__device__ float g_rotp[KCH * BB * OC * HWP];            // conv partial coord sums
__device__ uint  g_xt[(size_t)BB * HP * WP * 64];        // padded NHWC ch-paired fp16:
                                                         // [b][h][w][cp] = h2(x[cp],x[cp+64])

// ---------------- helpers ----------------
__device__ __forceinline__ void unpackf2(ull v, float& a, float& b) {
    asm("mov.b64 {%0, %1}, %2;" : "=f"(a), "=f"(b) : "l"(v));
}
__device__ __forceinline__ void fma2(ull& d, ull a, ull b) {
    asm("fma.rn.f32x2 %0, %1, %2, %0;" : "+l"(d) : "l"(a), "l"(b));
}
// fp16-pair -> packed f32x2 (storage-only quantization; accumulate stays fp32)
__device__ __forceinline__ ull h2tof2(uint raw) {
    float2 f = __half22float2(*(const __half2*)&raw);
    return *(const ull*)&f;
}
__device__ __forceinline__ uint packh2(float a, float b) {
    __half2 hv = __floats2half2_rn(a, b);
    return *(const uint*)&hv;
}
__device__ __forceinline__ __half2 u2h(uint v) { return *(const __half2*)&v; }
__device__ __forceinline__ uint h2u(__half2 v) { return *(const uint*)&v; }
// m16n8k16 fp16 mma, fp32 accumulate. Same mantissa width as tf32, 2x rate.
__device__ __forceinline__ void mma_f16(float* d, uint a0, uint a1, uint a2, uint a3,
                                        uint b0, uint b1) {
    asm("mma.sync.aligned.m16n8k16.row.col.f32.f16.f16.f32 "
        "{%0,%1,%2,%3},{%4,%5,%6,%7},{%8,%9},{%0,%1,%2,%3};"
        : "+f"(d[0]), "+f"(d[1]), "+f"(d[2]), "+f"(d[3])
        : "r"(a0), "r"(a1), "r"(a2), "r"(a3), "r"(b0), "r"(b1));
}
// fp16 bilinear blend: cf01 = h2(c00,c01), cf23 = h2(c10,c11); q0={g00,g01}, q1={g10,g11}
__device__ __forceinline__ uint hblend(uint cf01, uint cf23, uint2 q0, uint2 q1) {
    __half2 c00 = u2h(__byte_perm(cf01, 0, 0x1010));
    __half2 c01 = u2h(__byte_perm(cf01, 0, 0x3232));
    __half2 c10 = u2h(__byte_perm(cf23, 0, 0x1010));
    __half2 c11 = u2h(__byte_perm(cf23, 0, 0x3232));
    __half2 s = __hmul2(c00, u2h(q0.x));
    s = __hfma2(c01, u2h(q0.y), s);
    s = __hfma2(c10, u2h(q1.x), s);
    s = __hfma2(c11, u2h(q1.y), s);
    return h2u(s);
}

#define CONV_BLOCKS (BB * 24 * KCH)   // 384
#define TR_BLOCKS   1152              // 3 x 96 x 4
#define ZERO_BLOCKS 32
#define TOTAL_A     (CONV_BLOCKS + TR_BLOCKS + ZERO_BLOCKS)
#define XS_CSTRIDE  600               // per PAIR-plane stride (uints); %32=24 -> conflict-free
#define XS_RSTRIDE  100

// halo cells per batch: top 98 + bottom 98 + left 96 + right 96 = 388
#define HALO_CELLS  388
#define HALO_TOTAL  (BB * HALO_CELLS * 64)   // uint entries

// ============================================================================
// Fused kernel A: fp16-mma conv split-K (0..383, TWO 16-ch phases per block)
//                 + transpose (384..1535) + halo-zero (1536..1567).
// Conv per-phase code is the validated R13 single-phase body in an s-loop.
// ============================================================================
__global__ __launch_bounds__(256, 2)
void fusedA_kernel(const float* __restrict__ x, const float* __restrict__ rw)
{
    __shared__ union {
        struct {
            uint xs[8 * XS_CSTRIDE];  // 8 ch-pairs x (6 rows x 98 cols) half2
            uint ws[9 * 8 * 24];      // [tap][ch-pair][out] half2
        } cv;
        uint tr[64][33];
    } sm;

    const int tid = threadIdx.x;
    const int bi  = blockIdx.x;

    if (bi >= CONV_BLOCKS + TR_BLOCKS) {
        // -------------------- HALO-ZERO role --------------------
        const int zi = bi - (CONV_BLOCKS + TR_BLOCKS);
        for (int i = zi * 256 + tid; i < HALO_TOTAL; i += ZERO_BLOCKS * 256) {
            int b = i / (HALO_CELLS * 64);
            int r = i - b * (HALO_CELLS * 64);
            int cell = r >> 6, cp = r & 63;
            int hh, ww;
            if (cell < 98)       { hh = -1; ww = cell - 1; }
            else if (cell < 196) { hh = 96; ww = cell - 98 - 1; }
            else if (cell < 292) { hh = cell - 196; ww = -1; }
            else                 { hh = cell - 292; ww = 96; }
            g_xt[(((size_t)b * HP + (hh + 1)) * WP + (ww + 1)) * 64 + cp] = 0u;
        }
        return;
    }

    if (bi >= CONV_BLOCKS) {
        // -------------------- TRANSPOSE role (fp16 pack) --------------------
        const int ti = bi - CONV_BLOCKS;             // 0..1151 = 3 x 96 x 4
        const int w0 = (ti % 3) * 32;
        const int h  = (ti / 3) % 96;
        const int b  = ti / 288;
        const int tx = tid & 31, ty = tid >> 5;      // ty 0..7

        const float* xb = x + ((size_t)b * CC) * HWP + h * WW + w0;
        #pragma unroll
        for (int k = 0; k < 8; k++) {
            int c = ty + 8 * k;                      // 0..63
            float v0 = xb[(size_t)c * HWP + tx];
            float v1 = xb[(size_t)(c + 64) * HWP + tx];
            sm.tr[c][tx] = packh2(v0, v1);
        }
        __syncthreads();
        uint* ob = g_xt + (((size_t)b * HP + (h + 1)) * WP + (w0 + 1)) * 64;
        #pragma unroll
        for (int k = 0; k < 8; k++) {
            int cp = tx + 32 * (k & 1);
            int wl = ty + 8 * (k >> 1);
            ob[(size_t)wl * 64 + cp] = sm.tr[cp][wl];
        }
        return;
    }

    // -------------------- CONV role --------------------
    const int lane = tid & 31;
    const int warp = tid >> 5;        // 0..7
    const int g  = lane >> 2;         // groupID 0..7 (pixel row within m16)
    const int tg = lane & 3;          // threadID-in-group 0..3 (k selector)

    const int b     = bi / (24 * KCH);
    const int rest  = bi % (24 * KCH);
    const int h0    = (rest % 24) * 4;     // 4 image rows per block
    const int chunk = rest / 24;           // 0..3 -> channels [chunk*32, +32)

    float D[3][3][4];
    #pragma unroll
    for (int i = 0; i < 3; i++)
        #pragma unroll
        for (int j = 0; j < 3; j++)
            #pragma unroll
            for (int k = 0; k < 4; k++) D[i][j][k] = 0.0f;

    #pragma unroll 1
    for (int s = 0; s < 2; s++) {
        const int cbase = chunk * 32 + s * 16;   // 16-channel phase base
        __syncthreads();
        // ---- stage x as channel-paired half2: warp = pair (cbase+2w, +1). NO div.
        {
            const float* xg0 = x + ((size_t)(b * CC + cbase + 2 * warp)) * HWP;
            const float* xg1 = xg0 + HWP;
            uint* xrow = sm.cv.xs + warp * XS_CSTRIDE;
            #pragma unroll
            for (int rr = 0; rr < 6; rr++) {
                const int grow = h0 - 1 + rr;
                const bool rok = (unsigned)grow < (unsigned)HH;
                const float* xr0 = xg0 + grow * WW;
                const float* xr1 = xg1 + grow * WW;
                #pragma unroll
                for (int q = 0; q < 4; q++) {
                    const int cc = q * 32 + lane;
                    if (cc < 98) {
                        const int gcol = cc - 1;
                        const bool ok = rok && (unsigned)gcol < (unsigned)WW;
                        float v0 = ok ? xr0[gcol] : 0.0f;
                        float v1 = ok ? xr1[gcol] : 0.0f;
                        xrow[rr * XS_RSTRIDE + cc] = packh2(v0, v1);
                    }
                }
            }
        }
        // ---- stage w: ws[t][pair][o] = half2(w[2kp], w[2kp+1]) (o>=18 zero) ----
        for (int i = tid; i < 1728; i += 256) {
            int t = i / 192, rem = i - t * 192;
            int kp = rem / 24, o = rem - kp * 24;
            const int c0 = cbase + 2 * kp;
            float v0 = 0.0f, v1 = 0.0f;
            if (o < OC) {
                v0 = rw[((size_t)o * CC + c0) * 9 + t];
                v1 = rw[((size_t)o * CC + c0 + 1) * 9 + t];
            }
            sm.cv.ws[i] = packh2(v0, v1);
        }
        __syncthreads();

        #pragma unroll
        for (int kk = 0; kk < 9; kk++) {          // tap = kk ; k16 = 16 channels
            const int dr = kk / 3, dc = kk % 3;
            uint b0[3], b1[3];
            #pragma unroll
            for (int nt = 0; nt < 3; nt++) {
                b0[nt] = sm.cv.ws[kk * 192 + tg * 24 + nt * 8 + g];
                b1[nt] = sm.cv.ws[kk * 192 + (tg + 4) * 24 + nt * 8 + g];
            }
            #pragma unroll
            for (int mt = 0; mt < 3; mt++) {
                const int m  = warp + mt * 8;      // m16-tile 0..23
                const int r  = m / 6;              // row 0..3 within block
                const int cb = (m % 6) * 16;       // col base
                const int base = (r + dr) * XS_RSTRIDE + cb + dc + g;
                uint a0 = sm.cv.xs[tg * XS_CSTRIDE + base];
                uint a1 = sm.cv.xs[tg * XS_CSTRIDE + base + 8];
                uint a2 = sm.cv.xs[(tg + 4) * XS_CSTRIDE + base];
                uint a3 = sm.cv.xs[(tg + 4) * XS_CSTRIDE + base + 8];
                #pragma unroll
                for (int nt = 0; nt < 3; nt++)
                    mma_f16(D[mt][nt], a0, a1, a2, a3, b0[nt], b1[nt]);
            }
        }
    }

    // ---- epilogue: write raw coordinate partial sums ----
    float* rp = g_rotp + (size_t)(chunk * BB + b) * OC * HWP;
    #pragma unroll
    for (int mt = 0; mt < 3; mt++) {
        const int m  = warp + mt * 8;
        const int r  = m / 6;
        const int cb = (m % 6) * 16;
        const int pl = (h0 + r) * WW + cb + g;     // pixel offset within image
        #pragma unroll
        for (int nt = 0; nt < 3; nt++) {
            const int t = nt * 4 + tg;
            if (t > 8) continue;
            #pragma unroll
            for (int half = 0; half < 2; half++) {
                rp[(size_t)(2 * t)     * HWP + pl + half * 8] = D[mt][nt][2 * half];
                rp[(size_t)(2 * t + 1) * HWP + pl + half * 8] = D[mt][nt][2 * half + 1];
            }
        }
    }
}

// ============================================================================
// Kernel 2: fused coef + deform gather — single-wave launch geometry.
// 48-px tiles, grid (2, 96, 4) = 768 blocks <= 888 (148 SM x 6 CTAs) -> NO
// second-wave tail (R14's occ loss). Inner loop identical to R14 (validated).
// Block = 256 threads: cp(64) x pg(4), each pg = 12 px = 6 pixel-pairs.
// ============================================================================
__global__ __launch_bounds__(256, 6)
void deform_kernel(const float* __restrict__ wt, const float* __restrict__ rb,
                   float* __restrict__ out)
{
    __shared__ uint2 wtq[20][64];    // {h2(wL[s],wH[s]), h2(wL[s+1],wH[s+1])} (10 KB)
    __shared__ uint4 cfid[9][48];    // {h2(c00,c01), h2(c10,c11), quad_byte_off, 0} (6.9 KB)
    __shared__ uint  res[64][49];    // h2(out[cp], out[cp+64])  (12.5 KB)

    const int tid = threadIdx.x;
    const int cp = tid & 63;            // channel pair lane
    const int pg = tid >> 6;            // pixel group 0..3 -> pixels 12pg..12pg+11
    const int w0 = blockIdx.x * 48;
    const int h  = blockIdx.y;
    const int b  = blockIdx.z;
    const int px0 = pg * 12;

    // stage fp16 quad weight table (rows 16..19 zero-padded)
    for (int i = tid; i < 20 * 64; i += 256) {
        int s = i >> 6, c = i & 63;
        float wl0 = (s < 16)     ? wt[c * 16 + s]            : 0.0f;
        float wh0 = (s < 16)     ? wt[(c + 64) * 16 + s]     : 0.0f;
        float wl1 = (s + 1 < 16) ? wt[c * 16 + s + 1]        : 0.0f;
        float wh1 = (s + 1 < 16) ? wt[(c + 64) * 16 + s + 1] : 0.0f;
        wtq[s][c] = make_uint2(packh2(wl0, wh0), packh2(wl1, wh1));
    }

    // fused coef: items (t 0..8, p 0..47) = 432 ; sum KCH=4 partials + bias
    for (int i = tid; i < 432; i += 256) {
        int t = i / 48, p = i - t * 48;
        int off = h * WW + w0 + p;
        int o0 = 2 * t, o1 = 2 * t + 1;
        float chv = rb[o0] + 0.5f + (float)(t / 3);
        float cwv = rb[o1] + 0.5f + (float)(t % 3);
        #pragma unroll
        for (int ch = 0; ch < KCH; ch++) {
            const float* base = g_rotp + ((size_t)(ch * BB + b) * OC) * HWP + off;
            chv += base[(size_t)o0 * HWP];
            cwv += base[(size_t)o1 * HWP];
        }
        chv = fminf(fmaxf(chv, 0.0f), 3.0f);
        cwv = fminf(fmaxf(cwv, 0.0f), 3.0f);
        float h0f = floorf(chv), w0f = floorf(cwv);
        float lh = chv - h0f, lw = cwv - w0f;
        int h0i = (int)h0f, w0i = (int)w0f;
        float c00 = (1.0f - lh) * (1.0f - lw);
        float c01 = (1.0f - lh) * lw;
        float c10 = lh * (1.0f - lw);
        float c11 = lh * lw;
        cfid[t][p] = make_uint4(packh2(c00, c01), packh2(c10, c11),
                                (uint)(h0i * 4 + w0i) << 9, 0u);
    }
    __syncthreads();

    // row base pointers into the padded fp16 tensor (loop-invariant)
    const uint* xrow0 = g_xt + (((size_t)b * HP + h)     * WP) * 64 + cp;  // h-1
    const uint* xrow1 = g_xt + (((size_t)b * HP + h + 1) * WP) * 64 + cp;  // h
    const uint* xrow2 = g_xt + (((size_t)b * HP + h + 2) * WP) * 64 + cp;  // h+1
    const char* wbase = (const char*)&wtq[0][cp];

    ull xv[3][4];   // f32x2 (converted at load)
    #pragma unroll
    for (int dj = 0; dj < 2; dj++) {
        const int pc = (w0 + px0 + dj) * 64;       // padded col
        xv[0][dj] = h2tof2(xrow0[pc]);
        xv[1][dj] = h2tof2(xrow1[pc]);
        xv[2][dj] = h2tof2(xrow2[pc]);
    }

    #pragma unroll
    for (int pp = 0; pp < 6; pp++) {
        const int p0 = px0 + 2 * pp;
        #pragma unroll
        for (int dj = 2; dj < 4; dj++) {
            const int pc = (w0 + p0 + dj) * 64;
            xv[0][dj] = h2tof2(xrow0[pc]);
            xv[1][dj] = h2tof2(xrow1[pc]);
            xv[2][dj] = h2tof2(xrow2[pc]);
        }

        ull accA = 0ull, accB = 0ull;
        #pragma unroll
        for (int t = 0; t < 9; t++) {
            const int tr = t / 3, tc = t % 3;
            { // pixel A
                const uint4 cf = cfid[t][p0];                       // 1 uniform LDS.128
                const uint2 q0 = *(const uint2*)(wbase + cf.z);
                const uint2 q1 = *(const uint2*)(wbase + cf.z + 2048);
                uint s = hblend(cf.x, cf.y, q0, q1);
                fma2(accA, h2tof2(s), xv[tr][tc]);
            }
            { // pixel B
                const uint4 cf = cfid[t][p0 + 1];
                const uint2 q0 = *(const uint2*)(wbase + cf.z);
                const uint2 q1 = *(const uint2*)(wbase + cf.z + 2048);
                uint s = hblend(cf.x, cf.y, q0, q1);
                fma2(accB, h2tof2(s), xv[tr][tc + 1]);
            }
        }

        float aL, aH, bL, bH;
        unpackf2(accA, aL, aH);
        unpackf2(accB, bL, bH);
        res[cp][p0]     = packh2(aL, aH);
        res[cp][p0 + 1] = packh2(bL, bH);

        #pragma unroll
        for (int di = 0; di < 3; di++) { xv[di][0] = xv[di][2]; xv[di][1] = xv[di][3]; }
    }
    __syncthreads();

    // coalesced NCHW write: each thread writes (cp, p) and (cp+64, p)
    float* ob = out + (size_t)b * CC * HWP + h * WW + w0;
    for (int i = tid; i < 64 * 48; i += 256) {
        int c2 = i / 48, p = i - c2 * 48;
        float lo, hi;
        unpackf2(h2tof2(res[c2][p]), lo, hi);
        ob[(size_t)c2 * HWP + p]        = lo;
        ob[(size_t)(c2 + 64) * HWP + p] = hi;
    }
}

// ============================================================================
extern "C" void kernel_launch(void* const* d_in, const int* in_sizes, int n_in,
                              void* d_out, int out_size)
{
    const float* x  = (const float*)d_in[0];   // [4,128,96,96]
    const float* rw = (const float*)d_in[1];   // [18,128,3,3]
    const float* rb = (const float*)d_in[2];   // [18]
    const float* wt = (const float*)d_in[3];   // [128,4,4]
    float* out = (float*)d_out;                // [4,128,96,96]

    fusedA_kernel<<<TOTAL_A, 256>>>(x, rw);
    deform_kernel<<<dim3(2, HH, BB), 256>>>(wt, rb, out);
}